// round 14
// baseline (speedup 1.0000x reference)
#include <cuda_runtime.h>
#include <cuda_fp16.h>
#include <cstdint>
#include <math.h>

#define NB 16
#define SEQ 2048
#define DM 768

// ---------------- scratch (device globals) ----------------------------------
__device__ __half g_xt[(long long)NB * SEQ * DM];
__device__ __half g_xf[(long long)NB * SEQ * DM];
__device__ __half g_WqT[DM * DM];
__device__ __half g_WkT[DM * DM];
__device__ __half g_WvT[DM * DM];
__device__ __half g_Q[(long long)NB * SEQ * DM];    // pre-scaled by 1/sqrt(H)
__device__ __half g_K[(long long)NB * SEQ * DM];
__device__ __half g_VT[(long long)NB * SEQ * DM];   // [b][768][2048]
__device__ __half g_E[(long long)NB * SEQ * SEQ];   // exp(scores), fp16
__device__ float  g_part[(long long)NB * SEQ * 32]; // per-(colblock,warp) row partials
__device__ float  g_inv[(long long)NB * SEQ];       // 1 / rowsum(E)

// ---------------- PTX helpers ------------------------------------------------
__device__ __forceinline__ uint32_t smem_u32(const void* p) {
    return (uint32_t)__cvta_generic_to_shared(p);
}
__device__ __forceinline__ void cp_async16(uint32_t dst, const void* src) {
    asm volatile("cp.async.cg.shared.global.L2::256B [%0], [%1], 16;"
                 :: "r"(dst), "l"(src));
}
__device__ __forceinline__ void cp_commit() {
    asm volatile("cp.async.commit_group;" ::: "memory");
}
__device__ __forceinline__ void ldm_x4(uint32_t* d, uint32_t a) {
    asm volatile("ldmatrix.sync.aligned.m8n8.x4.shared.b16 {%0,%1,%2,%3}, [%4];"
                 : "=r"(d[0]), "=r"(d[1]), "=r"(d[2]), "=r"(d[3]) : "r"(a));
}
__device__ __forceinline__ void mma16816(float* c, const uint32_t* a, const uint32_t* b) {
    asm volatile("mma.sync.aligned.m16n8k16.row.col.f32.f16.f16.f32 "
                 "{%0,%1,%2,%3}, {%4,%5,%6,%7}, {%8,%9}, {%0,%1,%2,%3};"
                 : "+f"(c[0]), "+f"(c[1]), "+f"(c[2]), "+f"(c[3])
                 : "r"(a[0]), "r"(a[1]), "r"(a[2]), "r"(a[3]),
                   "r"(b[0]), "r"(b[1]));
}

// ============================================================================
// GEMM: C[M,N] = A[M,K] * B[N,K]^T, fp16 in, fp32 accum (mma.sync).
// BM=128, BN=128, BK=64, 3 stages SW128, 256 threads, PF=1, one sync/tile,
// 2 CTAs per SM (cross-CTA latency overlap). Warp tile 32x64 (4x2 warps).
// MODE: 0 *scale   1 +bias[n],*scale   2 +bias[m]
//       3 exp(acc) -> half, + row-partial sums to part[]
//       4 acc * rowscale[m]
// DUAL (MODE 1 only): blockIdx.z selects operand set.
// ============================================================================
template <int MODE, bool OUT_HALF, bool DUAL>
__global__ void __launch_bounds__(256, 2)
gemm_any(const __half* __restrict__ Ag, const __half* __restrict__ Bg,
         const float* __restrict__ bias, void* __restrict__ Cg,
         const __half* __restrict__ Ag2, const __half* __restrict__ Bg2,
         const float* __restrict__ bias2, void* __restrict__ Cg2,
         float* __restrict__ part,
         int Kd, int lda, int ldb, int ldc, float scale, float scale2,
         long long strA, long long strB, long long strC, long long strBias)
{
    constexpr int BM = 128, BN = 128, BK = 64, ST = 3, PF = 1;
    constexpr int ABYTES = BM * 128;            // 16 KB
    constexpr int BBYTES = BN * 128;            // 16 KB
    constexpr int STAGE  = ABYTES + BBYTES;     // 32 KB

    extern __shared__ char dsm[];
    const uint32_t smem0 = (smem_u32(dsm) + 1023u) & ~1023u;

    const int tid  = threadIdx.x;
    const int warp = tid >> 5;
    const int lane = tid & 31;
    const int z    = blockIdx.z;
    const int row0 = blockIdx.y * BM;
    const int col0 = blockIdx.x * BN;

    const __half* Az;
    const __half* Bz;
    const float*  bz;
    float sc;
    if constexpr (DUAL) {
        Az = z ? Ag2 : Ag;
        Bz = z ? Bg2 : Bg;
        bz = z ? bias2 : bias;
        sc = z ? scale2 : scale;
    } else {
        Az = Ag + (size_t)z * strA;
        Bz = Bg + (size_t)z * strB;
        bz = bias ? (bias + (size_t)z * strBias) : bias;
        sc = scale;
    }
    const int T = Kd / BK;

    auto load = [&](int s, int t) {
        const int kt = t * BK;
        const uint32_t abase = smem0 + s * STAGE;
        const uint32_t bbase = abase + ABYTES;
#pragma unroll
        for (int it = 0; it < 4; ++it) {            // A: 1024 x 16B
            int id = tid + it * 256;
            int r = id >> 3, cb = (id & 7) << 4;
            uint32_t off = (uint32_t)(r * 128 + cb);
            cp_async16(abase + (off ^ ((off >> 3) & 0x70)),
                       Az + (size_t)(row0 + r) * lda + kt + (cb >> 1));
        }
#pragma unroll
        for (int it = 0; it < 4; ++it) {            // B: 1024 x 16B
            int id = tid + it * 256;
            int r = id >> 3, cb = (id & 7) << 4;
            uint32_t off = (uint32_t)(r * 128 + cb);
            cp_async16(bbase + (off ^ ((off >> 3) & 0x70)),
                       Bz + (size_t)(col0 + r) * ldb + kt + (cb >> 1));
        }
    };

    const int wr = warp >> 1;       // 0..3 : 32-row slab
    const int wc = warp & 1;        // 0..1 : 64-col slab
    float acc[2][8][4];
#pragma unroll
    for (int i = 0; i < 2; ++i)
#pragma unroll
        for (int j = 0; j < 8; ++j)
#pragma unroll
            for (int r = 0; r < 4; ++r) acc[i][j][r] = 0.f;

    load(0, 0); cp_commit();

    for (int i = 0; i < T; ++i) {
        const int j = i + PF;
        if (j < T) load(j % ST, j);
        cp_commit();
        asm volatile("cp.async.wait_group 1;" ::: "memory");
        __syncthreads();

        const uint32_t ab = smem0 + (i % ST) * STAGE;
        const uint32_t bb = ab + ABYTES;
#pragma unroll
        for (int ks = 0; ks < 4; ++ks) {
            const int kb = ks * 32;
            const int rl = lane & 15;
            const int ch = kb + ((lane >> 4) << 4);
            uint32_t a[2][4], bq[4][4];
#pragma unroll
            for (int ii = 0; ii < 2; ++ii) {
                int row = wr * 32 + ii * 16 + rl;
                ldm_x4(a[ii], ab + row * 128 + (ch ^ ((row & 7) << 4)));
            }
#pragma unroll
            for (int jj = 0; jj < 4; ++jj) {
                int row = wc * 64 + jj * 16 + rl;
                ldm_x4(bq[jj], bb + row * 128 + (ch ^ ((row & 7) << 4)));
            }
#pragma unroll
            for (int ii = 0; ii < 2; ++ii)
#pragma unroll
                for (int jj = 0; jj < 4; ++jj) {
                    uint32_t b0[2] = { bq[jj][0], bq[jj][2] };
                    uint32_t b1[2] = { bq[jj][1], bq[jj][3] };
                    mma16816(acc[ii][2 * jj],     a[ii], b0);
                    mma16816(acc[ii][2 * jj + 1], a[ii], b1);
                }
        }
        // single sync/tile is safe: stage (i+1)%3 written at iter i was last
        // read at iter i-2; sync(i-1) orders those reads before this write
    }

    // ---- epilogue ----
    const int r0 = row0 + wr * 32 + (lane >> 2);
    const int c0 = col0 + wc * 64 + ((lane & 3) << 1);
    float rsum[2][2] = {{0.f, 0.f}, {0.f, 0.f}};

#pragma unroll
    for (int ii = 0; ii < 2; ++ii) {
        const int r = r0 + ii * 16;
        float rf0 = 0.f, rf8 = 0.f;
        if (MODE == 2 || MODE == 4) { rf0 = bz[r]; rf8 = bz[r + 8]; }
#pragma unroll
        for (int jj = 0; jj < 8; ++jj) {
            const int c = c0 + jj * 8;
            float v0 = acc[ii][jj][0], v1 = acc[ii][jj][1];
            float v2 = acc[ii][jj][2], v3 = acc[ii][jj][3];
            if (MODE == 1) {
                float b0 = bz[c], b1 = bz[c + 1];
                v0 = (v0 + b0) * sc; v1 = (v1 + b1) * sc;
                v2 = (v2 + b0) * sc; v3 = (v3 + b1) * sc;
            } else if (MODE == 2) {
                v0 += rf0; v1 += rf0; v2 += rf8; v3 += rf8;
            } else if (MODE == 3) {
                v0 = __expf(v0); v1 = __expf(v1);
                v2 = __expf(v2); v3 = __expf(v3);
                rsum[ii][0] += v0 + v1;
                rsum[ii][1] += v2 + v3;
            } else if (MODE == 4) {
                v0 *= rf0; v1 *= rf0; v2 *= rf8; v3 *= rf8;
            } else {
                v0 *= sc; v1 *= sc; v2 *= sc; v3 *= sc;
            }
            if constexpr (OUT_HALF) {
                __half* C = (__half*)((DUAL && z) ? Cg2 : Cg) +
                            (DUAL ? 0 : (size_t)z * strC);
                *(__half2*)(C + (size_t)r * ldc + c)       = __floats2half2_rn(v0, v1);
                *(__half2*)(C + (size_t)(r + 8) * ldc + c) = __floats2half2_rn(v2, v3);
            } else {
                float* C = (float*)((DUAL && z) ? Cg2 : Cg) +
                           (DUAL ? 0 : (size_t)z * strC);
                *(float2*)(C + (size_t)r * ldc + c)       = make_float2(v0, v1);
                *(float2*)(C + (size_t)(r + 8) * ldc + c) = make_float2(v2, v3);
            }
        }
    }

    if constexpr (MODE == 3) {
#pragma unroll
        for (int ii = 0; ii < 2; ++ii) {
#pragma unroll
            for (int h = 0; h < 2; ++h) {
                float s = rsum[ii][h];
                s += __shfl_xor_sync(0xffffffffu, s, 1);
                s += __shfl_xor_sync(0xffffffffu, s, 2);
                rsum[ii][h] = s;
            }
        }
        if ((lane & 3) == 0) {
            const int slot = blockIdx.x * 2 + wc;   // 16 colblocks x 2 warps = 32
#pragma unroll
            for (int ii = 0; ii < 2; ++ii) {
                const int r = r0 + ii * 16;
                part[((size_t)z * SEQ + r) * 32 + slot]       = rsum[ii][0];
                part[((size_t)z * SEQ + r + 8) * 32 + slot]   = rsum[ii][1];
            }
        }
    }
}

// ---------------- fp32 -> fp16 convert, both inputs in one launch ------------
__global__ void __launch_bounds__(256)
cvt2_k(const float4* __restrict__ in0, __half2* __restrict__ out0,
       const float4* __restrict__ in1, __half2* __restrict__ out1, int n4)
{
    int i = blockIdx.x * 256 + threadIdx.x;
    const float4* in = (i < n4) ? in0 : in1;
    __half2* out = (i < n4) ? out0 : out1;
    int k = (i < n4) ? i : (i - n4);
    float4 v = in[k];
    out[2 * k]     = __floats2half2_rn(v.x, v.y);
    out[2 * k + 1] = __floats2half2_rn(v.z, v.w);
}

// ---------------- fp32 [768,768] -> fp16 transposed, 3 weights in one launch -
__global__ void __launch_bounds__(256)
cvtT3_k(const float* __restrict__ w0, __half* __restrict__ o0,
        const float* __restrict__ w1, __half* __restrict__ o1,
        const float* __restrict__ w2, __half* __restrict__ o2)
{
    const int zz = blockIdx.z;
    const float* in = (zz == 0) ? w0 : (zz == 1) ? w1 : w2;
    __half* out = (zz == 0) ? o0 : (zz == 1) ? o1 : o2;

    __shared__ float t[32][33];
    const int bx = blockIdx.x * 32;
    const int by = blockIdx.y * 32;
    const int tx = threadIdx.x, ty = threadIdx.y;
#pragma unroll
    for (int yy = ty; yy < 32; yy += 8)
        t[yy][tx] = in[(size_t)(by + yy) * DM + bx + tx];
    __syncthreads();
#pragma unroll
    for (int yy = ty; yy < 32; yy += 8)
        out[(size_t)(bx + yy) * DM + by + tx] = __float2half(t[tx][yy]);
}

// ---------------- inv_k: inv[row] = 1 / sum(part[row][0:32]) -----------------
__global__ void __launch_bounds__(256)
inv_k(const float4* __restrict__ part, float* __restrict__ inv)
{
    const int row = blockIdx.x * 256 + threadIdx.x;   // 0 .. NB*SEQ-1
    const float4* p = part + (size_t)row * 8;
    float s = 0.f;
#pragma unroll
    for (int i = 0; i < 8; ++i) {
        float4 v = p[i];
        s += (v.x + v.y) + (v.z + v.w);
    }
    inv[row] = 1.0f / s;
}

// ---------------- launch ------------------------------------------------------
extern "C" void kernel_launch(void* const* d_in, const int* in_sizes, int n_in,
                              void* d_out, int out_size)
{
    const float* x_to   = (const float*)d_in[0];
    const float* x_from = (const float*)d_in[1];
    const float* Wq = (const float*)d_in[2];
    const float* bq = (const float*)d_in[3];
    const float* Wk = (const float*)d_in[4];
    const float* bk = (const float*)d_in[5];
    const float* Wv = (const float*)d_in[6];
    const float* bv = (const float*)d_in[7];
    float* out = (float*)d_out;

    void *pxt, *pxf, *pWqT, *pWkT, *pWvT, *pQ, *pK, *pVT, *pE, *pPart, *pInv;
    cudaGetSymbolAddress(&pxt, g_xt);
    cudaGetSymbolAddress(&pxf, g_xf);
    cudaGetSymbolAddress(&pWqT, g_WqT);
    cudaGetSymbolAddress(&pWkT, g_WkT);
    cudaGetSymbolAddress(&pWvT, g_WvT);
    cudaGetSymbolAddress(&pQ, g_Q);
    cudaGetSymbolAddress(&pK, g_K);
    cudaGetSymbolAddress(&pVT, g_VT);
    cudaGetSymbolAddress(&pE, g_E);
    cudaGetSymbolAddress(&pPart, g_part);
    cudaGetSymbolAddress(&pInv, g_inv);

    constexpr int SMEM = 3 * 32768 + 1024;   // 99,328 B per CTA (2 CTAs/SM)
    cudaFuncSetAttribute((const void*)gemm_any<1, true, true>,
                         cudaFuncAttributeMaxDynamicSharedMemorySize, SMEM);
    cudaFuncSetAttribute((const void*)gemm_any<2, true, false>,
                         cudaFuncAttributeMaxDynamicSharedMemorySize, SMEM);
    cudaFuncSetAttribute((const void*)gemm_any<3, true, false>,
                         cudaFuncAttributeMaxDynamicSharedMemorySize, SMEM);
    cudaFuncSetAttribute((const void*)gemm_any<4, false, false>,
                         cudaFuncAttributeMaxDynamicSharedMemorySize, SMEM);

    // converts
    const int nx4 = (NB * SEQ * DM) / 4;     // 6,291,456 = 24576 * 256
    cvt2_k<<<(2 * nx4) / 256, 256>>>((const float4*)x_to, (__half2*)pxt,
                                     (const float4*)x_from, (__half2*)pxf, nx4);
    dim3 tb(32, 8), tg(DM / 32, DM / 32, 3);
    cvtT3_k<<<tg, tb>>>(Wq, (__half*)pWqT, Wk, (__half*)pWkT, Wv, (__half*)pWvT);

    const float qscale = 1.0f / sqrtf((float)DM);

    // Q and K projections fused into one z=2 launch
    dim3 gqk(DM / 128, (NB * SEQ) / 128, 2);
    gemm_any<1, true, true><<<gqk, 256, SMEM>>>(
        (const __half*)pxt, (const __half*)pWqT, bq, pQ,
        (const __half*)pxf, (const __half*)pWkT, bk, pK,
        nullptr, DM, DM, DM, DM, qscale, 1.0f, 0, 0, 0, 0);

    // V^T = WvT * xf^T (+bv per row), batched
    dim3 gvt(SEQ / 128, DM / 128, NB);
    gemm_any<2, true, false><<<gvt, 256, SMEM>>>(
        (const __half*)pWvT, (const __half*)pxf, bv, pVT,
        nullptr, nullptr, nullptr, nullptr, nullptr,
        DM, DM, DM, SEQ, 1.0f, 0.f, 0, (long long)SEQ * DM, (long long)DM * SEQ, 0);

    // E = exp(Q * K^T) + row partial sums, batched, fp16 out
    dim3 gs(SEQ / 128, SEQ / 128, NB);
    gemm_any<3, true, false><<<gs, 256, SMEM>>>(
        (const __half*)pQ, (const __half*)pK, nullptr, pE,
        nullptr, nullptr, nullptr, nullptr, (float*)pPart,
        DM, DM, DM, SEQ, 1.0f, 0.f,
        (long long)SEQ * DM, (long long)SEQ * DM, (long long)SEQ * SEQ, 0);

    // inv[row] = 1 / sum of 32 partials (deterministic order)
    inv_k<<<(NB * SEQ) / 256, 256>>>((const float4*)pPart, (float*)pInv);

    // out = (E * V) * inv[row], batched, fp32 out
    dim3 go(DM / 128, SEQ / 128, NB);
    gemm_any<4, false, false><<<go, 256, SMEM>>>(
        (const __half*)pE, (const __half*)pVT, (const float*)pInv, out,
        nullptr, nullptr, nullptr, nullptr, nullptr,
        SEQ, SEQ, SEQ, DM, 1.0f, 0.f,
        (long long)SEQ * SEQ, (long long)DM * SEQ, (long long)SEQ * DM, SEQ);
}

// round 15
// speedup vs baseline: 1.0025x; 1.0025x over previous
#include <cuda_runtime.h>
#include <cuda_fp16.h>
#include <cstdint>
#include <math.h>

#define NB 16
#define SEQ 2048
#define DM 768

// ---------------- scratch (device globals) ----------------------------------
__device__ __half g_xt[(long long)NB * SEQ * DM];
__device__ __half g_xf[(long long)NB * SEQ * DM];
__device__ __half g_WqT[DM * DM];
__device__ __half g_WkT[DM * DM];
__device__ __half g_WvT[DM * DM];
__device__ __half g_Q[(long long)NB * SEQ * DM];    // pre-scaled by 1/sqrt(H)
__device__ __half g_K[(long long)NB * SEQ * DM];
__device__ __half g_VT[(long long)NB * SEQ * DM];   // [b][768][2048]
__device__ __half g_E[(long long)NB * SEQ * SEQ];   // exp(scores), fp16
__device__ float  g_part[(long long)NB * SEQ * 32]; // per-(colblock,warp) row partials
__device__ float  g_inv[(long long)NB * SEQ];       // 1 / rowsum(E)

// ---------------- PTX helpers ------------------------------------------------
__device__ __forceinline__ uint32_t smem_u32(const void* p) {
    return (uint32_t)__cvta_generic_to_shared(p);
}
__device__ __forceinline__ void cp_async16(uint32_t dst, const void* src) {
    asm volatile("cp.async.cg.shared.global [%0], [%1], 16;" :: "r"(dst), "l"(src));
}
__device__ __forceinline__ void cp_commit() {
    asm volatile("cp.async.commit_group;" ::: "memory");
}
__device__ __forceinline__ void ldm_x4(uint32_t* d, uint32_t a) {
    asm volatile("ldmatrix.sync.aligned.m8n8.x4.shared.b16 {%0,%1,%2,%3}, [%4];"
                 : "=r"(d[0]), "=r"(d[1]), "=r"(d[2]), "=r"(d[3]) : "r"(a));
}
__device__ __forceinline__ void mma16816(float* c, const uint32_t* a, const uint32_t* b) {
    asm volatile("mma.sync.aligned.m16n8k16.row.col.f32.f16.f16.f32 "
                 "{%0,%1,%2,%3}, {%4,%5,%6,%7}, {%8,%9}, {%0,%1,%2,%3};"
                 : "+f"(c[0]), "+f"(c[1]), "+f"(c[2]), "+f"(c[3])
                 : "r"(a[0]), "r"(a[1]), "r"(a[2]), "r"(a[3]),
                   "r"(b[0]), "r"(b[1]));
}

// ============================================================================
// GEMM: C[M,N] = A[M,K] * B[N,K]^T, fp16 in, fp32 accum (mma.sync).
// BM=128, BN=128, BK=64, 3 stages SW128, 256 threads, PF=1, one sync/tile,
// 2 CTAs per SM (cross-CTA latency overlap). Warp tile 32x64 (4x2 warps).
// MODE: 0 *scale   1 +bias[n],*scale   2 +bias[m]
//       3 exp(acc) -> half, + row-partial sums to part[]
//       4 acc * rowscale[m]
// DUAL (MODE 1 only): blockIdx.z selects operand set.
// ============================================================================
template <int MODE, bool OUT_HALF, bool DUAL>
__global__ void __launch_bounds__(256, 2)
gemm_any(const __half* __restrict__ Ag, const __half* __restrict__ Bg,
         const float* __restrict__ bias, void* __restrict__ Cg,
         const __half* __restrict__ Ag2, const __half* __restrict__ Bg2,
         const float* __restrict__ bias2, void* __restrict__ Cg2,
         float* __restrict__ part,
         int Kd, int lda, int ldb, int ldc, float scale, float scale2,
         long long strA, long long strB, long long strC, long long strBias)
{
    constexpr int BM = 128, BN = 128, BK = 64, ST = 3, PF = 1;
    constexpr int ABYTES = BM * 128;            // 16 KB
    constexpr int BBYTES = BN * 128;            // 16 KB
    constexpr int STAGE  = ABYTES + BBYTES;     // 32 KB

    extern __shared__ char dsm[];
    const uint32_t smem0 = (smem_u32(dsm) + 1023u) & ~1023u;

    const int tid  = threadIdx.x;
    const int warp = tid >> 5;
    const int lane = tid & 31;
    const int z    = blockIdx.z;
    const int row0 = blockIdx.y * BM;
    const int col0 = blockIdx.x * BN;

    const __half* Az;
    const __half* Bz;
    const float*  bz;
    float sc;
    if constexpr (DUAL) {
        Az = z ? Ag2 : Ag;
        Bz = z ? Bg2 : Bg;
        bz = z ? bias2 : bias;
        sc = z ? scale2 : scale;
    } else {
        Az = Ag + (size_t)z * strA;
        Bz = Bg + (size_t)z * strB;
        bz = bias ? (bias + (size_t)z * strBias) : bias;
        sc = scale;
    }
    const int T = Kd / BK;

    auto load = [&](int s, int t) {
        const int kt = t * BK;
        const uint32_t abase = smem0 + s * STAGE;
        const uint32_t bbase = abase + ABYTES;
#pragma unroll
        for (int it = 0; it < 4; ++it) {            // A: 1024 x 16B
            int id = tid + it * 256;
            int r = id >> 3, cb = (id & 7) << 4;
            uint32_t off = (uint32_t)(r * 128 + cb);
            cp_async16(abase + (off ^ ((off >> 3) & 0x70)),
                       Az + (size_t)(row0 + r) * lda + kt + (cb >> 1));
        }
#pragma unroll
        for (int it = 0; it < 4; ++it) {            // B: 1024 x 16B
            int id = tid + it * 256;
            int r = id >> 3, cb = (id & 7) << 4;
            uint32_t off = (uint32_t)(r * 128 + cb);
            cp_async16(bbase + (off ^ ((off >> 3) & 0x70)),
                       Bz + (size_t)(col0 + r) * ldb + kt + (cb >> 1));
        }
    };

    const int wr = warp >> 1;       // 0..3 : 32-row slab
    const int wc = warp & 1;        // 0..1 : 64-col slab
    float acc[2][8][4];
#pragma unroll
    for (int i = 0; i < 2; ++i)
#pragma unroll
        for (int j = 0; j < 8; ++j)
#pragma unroll
            for (int r = 0; r < 4; ++r) acc[i][j][r] = 0.f;

    load(0, 0); cp_commit();

    for (int i = 0; i < T; ++i) {
        const int j = i + PF;
        if (j < T) load(j % ST, j);
        cp_commit();
        asm volatile("cp.async.wait_group 1;" ::: "memory");
        __syncthreads();

        const uint32_t ab = smem0 + (i % ST) * STAGE;
        const uint32_t bb = ab + ABYTES;
#pragma unroll
        for (int ks = 0; ks < 4; ++ks) {
            const int kb = ks * 32;
            const int rl = lane & 15;
            const int ch = kb + ((lane >> 4) << 4);
            uint32_t a[2][4], bq[4][4];
#pragma unroll
            for (int ii = 0; ii < 2; ++ii) {
                int row = wr * 32 + ii * 16 + rl;
                ldm_x4(a[ii], ab + row * 128 + (ch ^ ((row & 7) << 4)));
            }
#pragma unroll
            for (int jj = 0; jj < 4; ++jj) {
                int row = wc * 64 + jj * 16 + rl;
                ldm_x4(bq[jj], bb + row * 128 + (ch ^ ((row & 7) << 4)));
            }
#pragma unroll
            for (int ii = 0; ii < 2; ++ii)
#pragma unroll
                for (int jj = 0; jj < 4; ++jj) {
                    uint32_t b0[2] = { bq[jj][0], bq[jj][2] };
                    uint32_t b1[2] = { bq[jj][1], bq[jj][3] };
                    mma16816(acc[ii][2 * jj],     a[ii], b0);
                    mma16816(acc[ii][2 * jj + 1], a[ii], b1);
                }
        }
        // single sync/tile is safe: stage (i+1)%3 written at iter i was last
        // read at iter i-2; sync(i-1) orders those reads before this write
    }

    // ---- epilogue ----
    const int r0 = row0 + wr * 32 + (lane >> 2);
    const int c0 = col0 + wc * 64 + ((lane & 3) << 1);
    float rsum[2][2] = {{0.f, 0.f}, {0.f, 0.f}};

#pragma unroll
    for (int ii = 0; ii < 2; ++ii) {
        const int r = r0 + ii * 16;
        float rf0 = 0.f, rf8 = 0.f;
        if (MODE == 2 || MODE == 4) { rf0 = bz[r]; rf8 = bz[r + 8]; }
#pragma unroll
        for (int jj = 0; jj < 8; ++jj) {
            const int c = c0 + jj * 8;
            float v0 = acc[ii][jj][0], v1 = acc[ii][jj][1];
            float v2 = acc[ii][jj][2], v3 = acc[ii][jj][3];
            if (MODE == 1) {
                float b0 = bz[c], b1 = bz[c + 1];
                v0 = (v0 + b0) * sc; v1 = (v1 + b1) * sc;
                v2 = (v2 + b0) * sc; v3 = (v3 + b1) * sc;
            } else if (MODE == 2) {
                v0 += rf0; v1 += rf0; v2 += rf8; v3 += rf8;
            } else if (MODE == 3) {
                v0 = __expf(v0); v1 = __expf(v1);
                v2 = __expf(v2); v3 = __expf(v3);
                rsum[ii][0] += v0 + v1;
                rsum[ii][1] += v2 + v3;
            } else if (MODE == 4) {
                v0 *= rf0; v1 *= rf0; v2 *= rf8; v3 *= rf8;
            } else {
                v0 *= sc; v1 *= sc; v2 *= sc; v3 *= sc;
            }
            if constexpr (OUT_HALF) {
                __half* C = (__half*)((DUAL && z) ? Cg2 : Cg) +
                            (DUAL ? 0 : (size_t)z * strC);
                *(__half2*)(C + (size_t)r * ldc + c)       = __floats2half2_rn(v0, v1);
                *(__half2*)(C + (size_t)(r + 8) * ldc + c) = __floats2half2_rn(v2, v3);
            } else {
                float* C = (float*)((DUAL && z) ? Cg2 : Cg) +
                           (DUAL ? 0 : (size_t)z * strC);
                *(float2*)(C + (size_t)r * ldc + c)       = make_float2(v0, v1);
                *(float2*)(C + (size_t)(r + 8) * ldc + c) = make_float2(v2, v3);
            }
        }
    }

    if constexpr (MODE == 3) {
#pragma unroll
        for (int ii = 0; ii < 2; ++ii) {
#pragma unroll
            for (int h = 0; h < 2; ++h) {
                float s = rsum[ii][h];
                s += __shfl_xor_sync(0xffffffffu, s, 1);
                s += __shfl_xor_sync(0xffffffffu, s, 2);
                rsum[ii][h] = s;
            }
        }
        if ((lane & 3) == 0) {
            const int slot = blockIdx.x * 2 + wc;   // 16 colblocks x 2 warps = 32
#pragma unroll
            for (int ii = 0; ii < 2; ++ii) {
                const int r = r0 + ii * 16;
                part[((size_t)z * SEQ + r) * 32 + slot]       = rsum[ii][0];
                part[((size_t)z * SEQ + r + 8) * 32 + slot]   = rsum[ii][1];
            }
        }
    }
}

// ---------------- fp32 -> fp16 convert, both inputs in one launch ------------
__global__ void __launch_bounds__(256)
cvt2_k(const float4* __restrict__ in0, __half2* __restrict__ out0,
       const float4* __restrict__ in1, __half2* __restrict__ out1, int n4)
{
    int i = blockIdx.x * 256 + threadIdx.x;
    const float4* in = (i < n4) ? in0 : in1;
    __half2* out = (i < n4) ? out0 : out1;
    int k = (i < n4) ? i : (i - n4);
    float4 v = in[k];
    out[2 * k]     = __floats2half2_rn(v.x, v.y);
    out[2 * k + 1] = __floats2half2_rn(v.z, v.w);
}

// ---------------- fp32 [768,768] -> fp16 transposed, 3 weights in one launch -
__global__ void __launch_bounds__(256)
cvtT3_k(const float* __restrict__ w0, __half* __restrict__ o0,
        const float* __restrict__ w1, __half* __restrict__ o1,
        const float* __restrict__ w2, __half* __restrict__ o2)
{
    const int zz = blockIdx.z;
    const float* in = (zz == 0) ? w0 : (zz == 1) ? w1 : w2;
    __half* out = (zz == 0) ? o0 : (zz == 1) ? o1 : o2;

    __shared__ float t[32][33];
    const int bx = blockIdx.x * 32;
    const int by = blockIdx.y * 32;
    const int tx = threadIdx.x, ty = threadIdx.y;
#pragma unroll
    for (int yy = ty; yy < 32; yy += 8)
        t[yy][tx] = in[(size_t)(by + yy) * DM + bx + tx];
    __syncthreads();
#pragma unroll
    for (int yy = ty; yy < 32; yy += 8)
        out[(size_t)(bx + yy) * DM + by + tx] = __float2half(t[tx][yy]);
}

// ---------------- inv_k: inv[row] = 1 / sum(part[row][0:32]) -----------------
__global__ void __launch_bounds__(256)
inv_k(const float4* __restrict__ part, float* __restrict__ inv)
{
    const int row = blockIdx.x * 256 + threadIdx.x;   // 0 .. NB*SEQ-1
    const float4* p = part + (size_t)row * 8;
    float s = 0.f;
#pragma unroll
    for (int i = 0; i < 8; ++i) {
        float4 v = p[i];
        s += (v.x + v.y) + (v.z + v.w);
    }
    inv[row] = 1.0f / s;
}

// ---------------- launch ------------------------------------------------------
extern "C" void kernel_launch(void* const* d_in, const int* in_sizes, int n_in,
                              void* d_out, int out_size)
{
    const float* x_to   = (const float*)d_in[0];
    const float* x_from = (const float*)d_in[1];
    const float* Wq = (const float*)d_in[2];
    const float* bq = (const float*)d_in[3];
    const float* Wk = (const float*)d_in[4];
    const float* bk = (const float*)d_in[5];
    const float* Wv = (const float*)d_in[6];
    const float* bv = (const float*)d_in[7];
    float* out = (float*)d_out;

    void *pxt, *pxf, *pWqT, *pWkT, *pWvT, *pQ, *pK, *pVT, *pE, *pPart, *pInv;
    cudaGetSymbolAddress(&pxt, g_xt);
    cudaGetSymbolAddress(&pxf, g_xf);
    cudaGetSymbolAddress(&pWqT, g_WqT);
    cudaGetSymbolAddress(&pWkT, g_WkT);
    cudaGetSymbolAddress(&pWvT, g_WvT);
    cudaGetSymbolAddress(&pQ, g_Q);
    cudaGetSymbolAddress(&pK, g_K);
    cudaGetSymbolAddress(&pVT, g_VT);
    cudaGetSymbolAddress(&pE, g_E);
    cudaGetSymbolAddress(&pPart, g_part);
    cudaGetSymbolAddress(&pInv, g_inv);

    constexpr int SMEM = 3 * 32768 + 1024;   // 99,328 B per CTA (2 CTAs/SM)
    cudaFuncSetAttribute((const void*)gemm_any<1, true, true>,
                         cudaFuncAttributeMaxDynamicSharedMemorySize, SMEM);
    cudaFuncSetAttribute((const void*)gemm_any<2, true, false>,
                         cudaFuncAttributeMaxDynamicSharedMemorySize, SMEM);
    cudaFuncSetAttribute((const void*)gemm_any<3, true, false>,
                         cudaFuncAttributeMaxDynamicSharedMemorySize, SMEM);
    cudaFuncSetAttribute((const void*)gemm_any<4, false, false>,
                         cudaFuncAttributeMaxDynamicSharedMemorySize, SMEM);

    // converts
    const int nx4 = (NB * SEQ * DM) / 4;     // 6,291,456 = 24576 * 256
    cvt2_k<<<(2 * nx4) / 256, 256>>>((const float4*)x_to, (__half2*)pxt,
                                     (const float4*)x_from, (__half2*)pxf, nx4);
    dim3 tb(32, 8), tg(DM / 32, DM / 32, 3);
    cvtT3_k<<<tg, tb>>>(Wq, (__half*)pWqT, Wk, (__half*)pWkT, Wv, (__half*)pWvT);

    const float qscale = 1.0f / sqrtf((float)DM);

    // Q and K projections fused into one z=2 launch
    dim3 gqk(DM / 128, (NB * SEQ) / 128, 2);
    gemm_any<1, true, true><<<gqk, 256, SMEM>>>(
        (const __half*)pxt, (const __half*)pWqT, bq, pQ,
        (const __half*)pxf, (const __half*)pWkT, bk, pK,
        nullptr, DM, DM, DM, DM, qscale, 1.0f, 0, 0, 0, 0);

    // V^T = WvT * xf^T (+bv per row), batched
    dim3 gvt(SEQ / 128, DM / 128, NB);
    gemm_any<2, true, false><<<gvt, 256, SMEM>>>(
        (const __half*)pWvT, (const __half*)pxf, bv, pVT,
        nullptr, nullptr, nullptr, nullptr, nullptr,
        DM, DM, DM, SEQ, 1.0f, 0.f, 0, (long long)SEQ * DM, (long long)DM * SEQ, 0);

    // E = exp(Q * K^T) + row partial sums, batched, fp16 out
    dim3 gs(SEQ / 128, SEQ / 128, NB);
    gemm_any<3, true, false><<<gs, 256, SMEM>>>(
        (const __half*)pQ, (const __half*)pK, nullptr, pE,
        nullptr, nullptr, nullptr, nullptr, (float*)pPart,
        DM, DM, DM, SEQ, 1.0f, 0.f,
        (long long)SEQ * DM, (long long)SEQ * DM, (long long)SEQ * SEQ, 0);

    // inv[row] = 1 / sum of 32 partials (deterministic order)
    inv_k<<<(NB * SEQ) / 256, 256>>>((const float4*)pPart, (float*)pInv);

    // out = (E * V) * inv[row], batched, fp32 out
    dim3 go(DM / 128, SEQ / 128, NB);
    gemm_any<4, false, false><<<go, 256, SMEM>>>(
        (const __half*)pE, (const __half*)pVT, (const float*)pInv, out,
        nullptr, nullptr, nullptr, nullptr, nullptr,
        SEQ, SEQ, SEQ, DM, 1.0f, 0.f,
        (long long)SEQ * SEQ, (long long)DM * SEQ, (long long)SEQ * DM, SEQ);
}